// round 2
// baseline (speedup 1.0000x reference)
#include <cuda_runtime.h>

// Output (1,64,64,64,32) fp32 = 8,388,608 floats = 2,097,152 float4.
// pos = (z,r,c) in 64^3 ; each pos broadcasts one gathered scalar into 32 floats (8 float4).
// thread tid: pos = tid >> 3, vec = tid & 7.  out[tid] = (v,v,v,v).
// src = inputs[ ((z_idx[z]*128 + row_idx[r])*128 + col_idx[c]) * 32 + 0 ]

__global__ __launch_bounds__(256) void sds3d_kernel(
    const float* __restrict__ in,
    const int* __restrict__ z_idx,
    const int* __restrict__ row_idx,
    const int* __restrict__ col_idx,
    float4* __restrict__ out)
{
    unsigned tid = blockIdx.x * 256u + threadIdx.x;   // 0 .. 2^21-1
    unsigned p   = tid >> 3;                          // gathered position 0..262143
    unsigned c   = p & 63u;
    unsigned r   = (p >> 6) & 63u;
    unsigned z   = p >> 12;

    int zi = __ldg(&z_idx[z]);
    int ri = __ldg(&row_idx[r]);
    int ci = __ldg(&col_idx[c]);

    unsigned src = ((unsigned)zi * 128u + (unsigned)ri) * 128u + (unsigned)ci;
    float v = __ldg(&in[src * 32u]);

    out[tid] = make_float4(v, v, v, v);
}

extern "C" void kernel_launch(void* const* d_in, const int* in_sizes, int n_in,
                              void* d_out, int out_size)
{
    const float* in      = (const float*)d_in[0];
    const int*   z_idx   = (const int*)d_in[1];
    const int*   row_idx = (const int*)d_in[2];
    const int*   col_idx = (const int*)d_in[3];
    float4* out = (float4*)d_out;

    // 2,097,152 float4 / 256 threads = 8192 blocks
    sds3d_kernel<<<8192, 256>>>(in, z_idx, row_idx, col_idx, out);
}

// round 3
// speedup vs baseline: 1.0029x; 1.0029x over previous
#include <cuda_runtime.h>

// Output (1,64,64,64,32) fp32 = 2,097,152 float4.
// position p = out_float4_index >> 3 ;  (z,r,c) = (p>>12, (p>>6)&63, p&63)
// src scalar = in[ ((z_idx[z]*128 + row_idx[r])*128 + col_idx[c]) * 32 ]
//
// K=4 independent chains per thread, spaced by S = 2^21/4 float4 = 65536
// positions = 16 z-groups: r and c identical across the 4 chains, only z
// differs (z, z+16, z+32, z+48). This gives MLP=4 on the gather loads while
// keeping stores perfectly coalesced and sharing row/col index loads.

#define K_ILP 4
#define S_F4  (2097152u / K_ILP)   // 524288 float4 stride between chains

__global__ __launch_bounds__(256) void sds3d_kernel(
    const float* __restrict__ in,
    const int* __restrict__ z_idx,
    const int* __restrict__ row_idx,
    const int* __restrict__ col_idx,
    float4* __restrict__ out)
{
    unsigned tid = blockIdx.x * 256u + threadIdx.x;   // 0 .. S_F4-1
    unsigned p   = tid >> 3;                          // position 0..65535 (z in 0..15)
    unsigned c   = p & 63u;
    unsigned r   = (p >> 6) & 63u;
    unsigned z0  = p >> 12;                           // 0..15

    int ri = __ldg(&row_idx[r]);
    int ci = __ldg(&col_idx[c]);
    unsigned rc = (unsigned)ri * 128u + (unsigned)ci; // partial address, shared

    // 4 independent gather chains
    int zi[K_ILP];
#pragma unroll
    for (int k = 0; k < K_ILP; k++)
        zi[k] = __ldg(&z_idx[z0 + 16u * k]);

    float v[K_ILP];
#pragma unroll
    for (int k = 0; k < K_ILP; k++) {
        unsigned src = ((unsigned)zi[k] * 16384u + rc) * 32u;
        v[k] = __ldg(&in[src]);
    }

#pragma unroll
    for (int k = 0; k < K_ILP; k++) {
        float4 o = make_float4(v[k], v[k], v[k], v[k]);
        __stcs(&out[tid + k * S_F4], o);              // streaming store
    }
}

extern "C" void kernel_launch(void* const* d_in, const int* in_sizes, int n_in,
                              void* d_out, int out_size)
{
    const float* in      = (const float*)d_in[0];
    const int*   z_idx   = (const int*)d_in[1];
    const int*   row_idx = (const int*)d_in[2];
    const int*   col_idx = (const int*)d_in[3];
    float4* out = (float4*)d_out;

    // S_F4 threads / 256 = 2048 blocks
    sds3d_kernel<<<S_F4 / 256, 256>>>(in, z_idx, row_idx, col_idx, out);
}